// round 3
// baseline (speedup 1.0000x reference)
#include <cuda_runtime.h>

#define BB 16
#define NN 4096
#define CC 1024
#define HH 16
#define DD 64

typedef unsigned long long u64;

__device__ __forceinline__ u64 pack2(float lo, float hi) {
    u64 r; asm("mov.b64 %0, {%1, %2};" : "=l"(r) : "f"(lo), "f"(hi)); return r;
}
__device__ __forceinline__ void unpack2(u64 v, float& lo, float& hi) {
    asm("mov.b64 {%0, %1}, %2;" : "=f"(lo), "=f"(hi) : "l"(v));
}
__device__ __forceinline__ void ffma2(u64& d, u64 a, u64 b) {
    asm("fma.rn.f32x2 %0, %1, %2, %0;" : "+l"(d) : "l"(a), "l"(b));
}

// Persistent scratch (allocation-free rule: __device__ globals)
__device__ float g_watt[BB*HH*CC];    // folded attention weights  [b][h][c]
__device__ float g_att[BB*HH*NN];     // logits, then exp values   [b][h][n]
__device__ float g_denom[BB*HH];      // softmax denominators
__device__ float g_xa[BB*HH*CC];      // attn-weighted x           [b][h][c]
__device__ float g_cls[BB*CC];        // cls embedding             [b][h*64+d]

// ---------------------------------------------------------------------------
// Kernel 1: per (b,h): q = scale * x[b,0,:] @ Wq[:,h,:]; then
// w_att[b,h,c] = sum_d Wkv_k[c,h,d] * q[d].
// ---------------------------------------------------------------------------
__global__ void k_watt(const float* __restrict__ x,
                       const float* __restrict__ Wq,
                       const float* __restrict__ Wkv) {
    int b = blockIdx.x >> 4;
    int h = blockIdx.x & 15;
    int t = threadIdx.x;   // 256 threads
    __shared__ float xs[CC];
    __shared__ float qpart[256];
    __shared__ float qs[DD];

    const float* xrow = x + (size_t)b * NN * CC;   // token 0 of batch b
    for (int c = t; c < CC; c += 256) xs[c] = xrow[c];
    __syncthreads();

    {
        int d = t >> 2, part = t & 3;
        const float* wq = Wq + h * DD + d;
        float acc = 0.f;
        int c0 = part * 256;
        #pragma unroll 8
        for (int c = c0; c < c0 + 256; ++c)
            acc += xs[c] * wq[(size_t)c * (HH * DD)];
        qpart[t] = acc;
    }
    __syncthreads();
    if (t < DD) {
        float q = qpart[t*4] + qpart[t*4+1] + qpart[t*4+2] + qpart[t*4+3];
        qs[t] = q * 0.125f;   // scale = D^-0.5 = 1/8
    }
    __syncthreads();

    for (int c = t; c < CC; c += 256) {
        const float4* wk = (const float4*)(Wkv + (size_t)c * (2*HH*DD) + h * DD);
        float s = 0.f;
        #pragma unroll
        for (int j4 = 0; j4 < DD/4; ++j4) {
            float4 w = wk[j4];
            s += w.x * qs[j4*4+0] + w.y * qs[j4*4+1]
               + w.z * qs[j4*4+2] + w.w * qs[j4*4+3];
        }
        g_watt[((size_t)b*HH + h)*CC + c] = s;
    }
}

// ---------------------------------------------------------------------------
// Kernel 2 (big pass 1): logits[b,h,n] = x[b,n,:] . w_att[b,h,:]
// hg = t&3 -> heads {hg,hg+4,hg+8,hg+12} in packed regs; sidx = t>>2 ->
// 16-float c-slice. Prefetch ring of 2 rows; per-row shuffle reduce;
// smem epilogue batched over 8 rows (2 syncs / 8 rows).
// ---------------------------------------------------------------------------
#define LR 64
__global__ void __launch_bounds__(256, 2) k_logits(const float* __restrict__ x) {
    int b      = blockIdx.y;
    int n_base = blockIdx.x * LR;
    int t      = threadIdx.x;
    int hg     = t & 3;
    int sidx   = t >> 2;      // 0..63
    int lane   = t & 31;
    int w      = t >> 5;      // warp id 0..7

    __shared__ float s_red[8*8*16];   // [r8][warp][head]  4 KB

    // w_att for 4 heads x 16 c-values, packed (8 x f32x2 per head)
    u64 w2[4][8];
    #pragma unroll
    for (int g = 0; g < 4; ++g) {
        const ulonglong2* wp =
            (const ulonglong2*)(g_watt + ((size_t)b*HH + hg + 4*g)*CC + sidx*16);
        #pragma unroll
        for (int j = 0; j < 4; ++j) {
            ulonglong2 v = wp[j];
            w2[g][2*j]   = v.x;
            w2[g][2*j+1] = v.y;
        }
    }

    const float* xb = x + (size_t)b*NN*CC + sidx*16;

    // prefetch ring of 2 rows (each row slice = 8 packed pairs)
    u64 buf[2][8];
    #pragma unroll
    for (int k = 0; k < 2; ++k) {
        const ulonglong2* xp = (const ulonglong2*)(xb + (size_t)(n_base + k)*CC);
        #pragma unroll
        for (int j = 0; j < 4; ++j) {
            ulonglong2 v = xp[j];
            buf[k][2*j]   = v.x;
            buf[k][2*j+1] = v.y;
        }
    }

    for (int n0 = 0; n0 < LR; n0 += 8) {
        #pragma unroll
        for (int r = 0; r < 8; ++r) {
            int nl   = n0 + r;
            int slot = nl & 1;

            u64 xx[8];
            #pragma unroll
            for (int j = 0; j < 8; ++j) xx[j] = buf[slot][j];

            // prefetch row nl+2 into the slot just freed
            int np = (nl + 2 < LR) ? nl + 2 : nl;
            const ulonglong2* xp = (const ulonglong2*)(xb + (size_t)(n_base + np)*CC);
            #pragma unroll
            for (int j = 0; j < 4; ++j) {
                ulonglong2 v = xp[j];
                buf[slot][2*j]   = v.x;
                buf[slot][2*j+1] = v.y;
            }

            u64 p2[4] = {0ull, 0ull, 0ull, 0ull};
            #pragma unroll
            for (int g = 0; g < 4; ++g)
                #pragma unroll
                for (int j = 0; j < 8; ++j)
                    ffma2(p2[g], xx[j], w2[g][j]);

            float pv[4];
            #pragma unroll
            for (int g = 0; g < 4; ++g) {
                float lo, hi; unpack2(p2[g], lo, hi);
                float v = lo + hi;
                v += __shfl_xor_sync(0xffffffffu, v, 4);
                v += __shfl_xor_sync(0xffffffffu, v, 8);
                v += __shfl_xor_sync(0xffffffffu, v, 16);
                pv[g] = v;
            }
            if (lane < 4) {
                #pragma unroll
                for (int g = 0; g < 4; ++g)
                    s_red[(r*8 + w)*16 + lane + 4*g] = pv[g];
            }
        }
        __syncthreads();
        if (t < 128) {
            int r = t >> 4, h = t & 15;
            float s = 0.f;
            #pragma unroll
            for (int ww = 0; ww < 8; ++ww) s += s_red[(r*8 + ww)*16 + h];
            g_att[((size_t)b*HH + h)*NN + n_base + n0 + r] = s;
        }
        __syncthreads();
    }
}

// ---------------------------------------------------------------------------
// Kernel 3: softmax over n per (b,h); exp in place + denom; zero g_xa.
// ---------------------------------------------------------------------------
__global__ void k_softmax() {
    int bh = blockIdx.x;              // 0..255
    int t  = threadIdx.x;             // 256
    float4* row4 = (float4*)(g_att + (size_t)bh * NN);
    __shared__ float sred[256];

    for (int i = t; i < CC; i += 256) g_xa[(size_t)bh*CC + i] = 0.f;

    float m = -1e30f;
    #pragma unroll
    for (int i = t; i < NN/4; i += 256) {
        float4 v = row4[i];
        m = fmaxf(m, fmaxf(fmaxf(v.x, v.y), fmaxf(v.z, v.w)));
    }
    sred[t] = m; __syncthreads();
    for (int s = 128; s > 0; s >>= 1) {
        if (t < s) sred[t] = fmaxf(sred[t], sred[t+s]);
        __syncthreads();
    }
    m = sred[0]; __syncthreads();

    float sum = 0.f;
    #pragma unroll
    for (int i = t; i < NN/4; i += 256) {
        float4 v = row4[i];
        v.x = __expf(v.x - m); v.y = __expf(v.y - m);
        v.z = __expf(v.z - m); v.w = __expf(v.w - m);
        row4[i] = v;
        sum += (v.x + v.y) + (v.z + v.w);
    }
    sred[t] = sum; __syncthreads();
    for (int s = 128; s > 0; s >>= 1) {
        if (t < s) sred[t] += sred[t+s];
        __syncthreads();
    }
    if (t == 0) g_denom[bh] = sred[0];
}

// ---------------------------------------------------------------------------
// Kernel 4 (big pass 2): xa[b,h,c] += sum_n p[b,h,n] * x[b,n,c]
// Thread owns 4 contiguous c's x all 16 heads; packed f32x2 accumulators.
// Prefetch ring of 4 rows for MLP=4 (hides 577-cyc DRAM latency).
// ---------------------------------------------------------------------------
#define XA_ROWS 64
__global__ void __launch_bounds__(256, 2) k_xa(const float* __restrict__ x) {
    int b      = blockIdx.y;
    int n_base = blockIdx.x * XA_ROWS;
    int t      = threadIdx.x;

    __shared__ __align__(16) float ps[XA_ROWS * 16];   // [n_local][h]  4 KB
    {
        int h = t & 15, ng = t >> 4;     // ng 0..15 -> rows ng*4..ng*4+3
        const float* ar = g_att + ((size_t)b*HH + h)*NN + n_base + ng*4;
        float4 a4 = *(const float4*)ar;
        ps[(ng*4+0)*16 + h] = a4.x;
        ps[(ng*4+1)*16 + h] = a4.y;
        ps[(ng*4+2)*16 + h] = a4.z;
        ps[(ng*4+3)*16 + h] = a4.w;
    }
    __syncthreads();

    int c0 = t * 4;
    const float* xp = x + ((size_t)b*NN + n_base)*CC + c0;

    u64 acc[8][4];
    #pragma unroll
    for (int hp = 0; hp < 8; ++hp)
        #pragma unroll
        for (int cj = 0; cj < 4; ++cj) acc[hp][cj] = 0ull;

    // prefetch ring of 4 rows
    float4 buf[4];
    #pragma unroll
    for (int k = 0; k < 4; ++k)
        buf[k] = *(const float4*)(xp + (size_t)k * CC);

    #pragma unroll 4
    for (int nl = 0; nl < XA_ROWS; ++nl) {
        int slot = nl & 3;
        float4 xv = buf[slot];

        // prefetch row nl+4 into the slot just freed
        int np = (nl + 4 < XA_ROWS) ? nl + 4 : nl;
        buf[slot] = *(const float4*)(xp + (size_t)np * CC);

        const ulonglong2* pr = (const ulonglong2*)(ps + nl*16);
        ulonglong2 q0 = pr[0], q1 = pr[1], q2 = pr[2], q3 = pr[3];
        u64 pp[8] = {q0.x, q0.y, q1.x, q1.y, q2.x, q2.y, q3.x, q3.y};

        u64 xx0 = pack2(xv.x, xv.x);
        u64 xx1 = pack2(xv.y, xv.y);
        u64 xx2 = pack2(xv.z, xv.z);
        u64 xx3 = pack2(xv.w, xv.w);

        #pragma unroll
        for (int hp = 0; hp < 8; ++hp) {
            ffma2(acc[hp][0], pp[hp], xx0);
            ffma2(acc[hp][1], pp[hp], xx1);
            ffma2(acc[hp][2], pp[hp], xx2);
            ffma2(acc[hp][3], pp[hp], xx3);
        }
    }

    #pragma unroll
    for (int hp = 0; hp < 8; ++hp) {
        float* d0 = g_xa + ((size_t)b*HH + 2*hp    )*CC + c0;
        float* d1 = g_xa + ((size_t)b*HH + 2*hp + 1)*CC + c0;
        #pragma unroll
        for (int cj = 0; cj < 4; ++cj) {
            float lo, hi; unpack2(acc[hp][cj], lo, hi);
            atomicAdd(d0 + cj, lo);
            atomicAdd(d1 + cj, hi);
        }
    }
}

// ---------------------------------------------------------------------------
// Kernel 5: cls[b,h,d] = (1/denom) * sum_c xa[b,h,c] * Wkv_v[c,h,d]
// Also seeds out with bproj (k_proj atomic-adds on top).
// ---------------------------------------------------------------------------
__global__ void k_cls(const float* __restrict__ Wkv,
                      const float* __restrict__ bproj,
                      float* __restrict__ out) {
    int b = blockIdx.x >> 4, h = blockIdx.x & 15;
    int d = threadIdx.x;   // 64
    __shared__ float xas[CC];
    const float* xa = g_xa + ((size_t)b*HH + h)*CC;
    for (int c = d; c < CC; c += 64) xas[c] = xa[c];
    __syncthreads();

    const float* wv = Wkv + (HH*DD) + h*DD + d;   // v-half column offset 1024
    float acc = 0.f;
    #pragma unroll 8
    for (int c = 0; c < CC; ++c)
        acc += xas[c] * wv[(size_t)c * (2*HH*DD)];

    float inv = 1.0f / g_denom[b*HH + h];
    int col = h*DD + d;
    g_cls[(size_t)b*CC + col] = acc * inv;
    out[(size_t)b*CC + col]   = bproj[col];
}

// ---------------------------------------------------------------------------
// Kernel 6: out[b,j] += sum_i cls[b,i] * Wproj[i,j]
// ---------------------------------------------------------------------------
__global__ void k_proj(const float* __restrict__ Wproj,
                       float* __restrict__ out) {
    int jc = blockIdx.x;   // 0..3
    int ic = blockIdx.y;   // 0..3
    int b  = blockIdx.z;   // 0..15
    int tt = threadIdx.x;  // 256
    int j  = jc*256 + tt;

    __shared__ float cs[256];
    cs[tt] = g_cls[(size_t)b*CC + ic*256 + tt];
    __syncthreads();

    const float* wp = Wproj + (size_t)(ic*256) * CC + j;
    float acc = 0.f;
    #pragma unroll 8
    for (int i = 0; i < 256; ++i)
        acc += cs[i] * wp[(size_t)i * CC];
    atomicAdd(&out[(size_t)b*CC + j], acc);
}

// ---------------------------------------------------------------------------
extern "C" void kernel_launch(void* const* d_in, const int* in_sizes, int n_in,
                              void* d_out, int out_size) {
    const float* x     = (const float*)d_in[0];
    const float* Wq    = (const float*)d_in[1];
    const float* Wkv   = (const float*)d_in[2];
    const float* Wproj = (const float*)d_in[3];
    const float* bproj = (const float*)d_in[4];
    float* out = (float*)d_out;

    k_watt   <<<BB*HH, 256>>>(x, Wq, Wkv);
    k_logits <<<dim3(NN/LR, BB), 256>>>(x);
    k_softmax<<<BB*HH, 256>>>();
    k_xa     <<<dim3(NN/XA_ROWS, BB), 256>>>(x);
    k_cls    <<<BB*HH, 64>>>(Wkv, bproj, out);
    k_proj   <<<dim3(4, 4, BB), 256>>>(Wproj, out);
}

// round 4
// speedup vs baseline: 1.0777x; 1.0777x over previous
#include <cuda_runtime.h>

#define BB 16
#define NN 4096
#define CC 1024
#define HH 16
#define DD 64

typedef unsigned long long u64;

__device__ __forceinline__ u64 pack2(float lo, float hi) {
    u64 r; asm("mov.b64 %0, {%1, %2};" : "=l"(r) : "f"(lo), "f"(hi)); return r;
}
__device__ __forceinline__ void unpack2(u64 v, float& lo, float& hi) {
    asm("mov.b64 {%0, %1}, %2;" : "=f"(lo), "=f"(hi) : "l"(v));
}
__device__ __forceinline__ void ffma2(u64& d, u64 a, u64 b) {
    asm("fma.rn.f32x2 %0, %1, %2, %0;" : "+l"(d) : "l"(a), "l"(b));
}

// cp.async helpers (LDGSTS, 16B)
__device__ __forceinline__ void cp16(float* dst_smem, const float* src_gmem) {
    unsigned d = (unsigned)__cvta_generic_to_shared(dst_smem);
    asm volatile("cp.async.cg.shared.global [%0], [%1], 16;" :: "r"(d), "l"(src_gmem));
}
__device__ __forceinline__ void cp_commit() {
    asm volatile("cp.async.commit_group;" ::: "memory");
}
template<int N> __device__ __forceinline__ void cp_wait() {
    asm volatile("cp.async.wait_group %0;" :: "n"(N) : "memory");
}

#define XPARTS 32   // k_xa partial sets

// Persistent scratch (allocation-free rule: __device__ globals)
__device__ float g_watt[BB*HH*CC];          // folded attention weights [b][h][c]
__device__ float g_att[BB*HH*NN];           // logits, then exp values  [b][h][n]
__device__ float g_denom[BB*HH];            // softmax denominators
__device__ float g_xap[XPARTS*BB*HH*CC];    // xa partials              [p][b][h][c]
__device__ float g_xa[BB*HH*CC];            // attn-weighted x          [b][h][c]
__device__ float g_cls[BB*CC];              // cls embedding            [b][h*64+d]

// ---------------------------------------------------------------------------
// Kernel 1: per (b,h): q = scale * x[b,0,:] @ Wq[:,h,:]; then
// w_att[b,h,c] = sum_d Wkv_k[c,h,d] * q[d].
// ---------------------------------------------------------------------------
__global__ void k_watt(const float* __restrict__ x,
                       const float* __restrict__ Wq,
                       const float* __restrict__ Wkv) {
    int b = blockIdx.x >> 4;
    int h = blockIdx.x & 15;
    int t = threadIdx.x;   // 256 threads
    __shared__ float xs[CC];
    __shared__ float qpart[256];
    __shared__ float qs[DD];

    const float* xrow = x + (size_t)b * NN * CC;   // token 0 of batch b
    for (int c = t; c < CC; c += 256) xs[c] = xrow[c];
    __syncthreads();

    {
        int d = t >> 2, part = t & 3;
        const float* wq = Wq + h * DD + d;
        float acc = 0.f;
        int c0 = part * 256;
        #pragma unroll 8
        for (int c = c0; c < c0 + 256; ++c)
            acc += xs[c] * wq[(size_t)c * (HH * DD)];
        qpart[t] = acc;
    }
    __syncthreads();
    if (t < DD) {
        float q = qpart[t*4] + qpart[t*4+1] + qpart[t*4+2] + qpart[t*4+3];
        qs[t] = q * 0.125f;   // scale = D^-0.5 = 1/8
    }
    __syncthreads();

    for (int c = t; c < CC; c += 256) {
        const float4* wk = (const float4*)(Wkv + (size_t)c * (2*HH*DD) + h * DD);
        float s = 0.f;
        #pragma unroll
        for (int j4 = 0; j4 < DD/4; ++j4) {
            float4 w = wk[j4];
            s += w.x * qs[j4*4+0] + w.y * qs[j4*4+1]
               + w.z * qs[j4*4+2] + w.w * qs[j4*4+3];
        }
        g_watt[((size_t)b*HH + h)*CC + c] = s;
    }
}

// ---------------------------------------------------------------------------
// Kernel 2 (big pass 1): logits[b,h,n] = x[b,n,:] . w_att[b,h,:]
// x staged via cp.async (2 batches x 4 rows in flight). hg = t&3 -> heads
// {hg,hg+4,hg+8,hg+12} packed in regs; sidx = t>>2 -> 16-float c-slice read
// from smem with XOR-swizzled chunk order (conflict-free LDS.128).
// ---------------------------------------------------------------------------
#define LR 64
#define LB 4
__global__ void __launch_bounds__(256, 2) k_logits(const float* __restrict__ x) {
    int b      = blockIdx.y;
    int n_base = blockIdx.x * LR;
    int t      = threadIdx.x;
    int hg     = t & 3;
    int sidx   = t >> 2;      // 0..63
    int lane   = t & 31;
    int w      = t >> 5;      // warp id 0..7

    __shared__ __align__(16) float xs[2][LB*CC];   // 2 x 16 KB
    __shared__ float s_red[LB*8*16];               // 2 KB

    // w_att for 4 heads x 16 c-values, packed (8 x f32x2 per head)
    u64 w2[4][8];
    #pragma unroll
    for (int g = 0; g < 4; ++g) {
        const ulonglong2* wp =
            (const ulonglong2*)(g_watt + ((size_t)b*HH + hg + 4*g)*CC + sidx*16);
        #pragma unroll
        for (int j = 0; j < 4; ++j) {
            ulonglong2 v = wp[j];
            w2[g][2*j]   = v.x;
            w2[g][2*j+1] = v.y;
        }
    }

    const float* xb = x + ((size_t)b*NN + n_base)*CC;

    // stage batch bt (rows bt*LB .. bt*LB+LB) into xs[bt&1]
    #define L_ISSUE(bt) do {                                              \
        const float* _s = xb + (size_t)(bt)*LB*CC + t*4;                  \
        float* _d = xs[(bt)&1] + t*4;                                     \
        _Pragma("unroll")                                                 \
        for (int _r = 0; _r < LB; ++_r) cp16(_d + _r*CC, _s + _r*CC);     \
        cp_commit();                                                      \
    } while (0)

    L_ISSUE(0);
    L_ISSUE(1);

    int swz = (sidx >> 1) & 3;

    for (int bt = 0; bt < LR/LB; ++bt) {
        if (bt + 1 < LR/LB) cp_wait<1>(); else cp_wait<0>();
        __syncthreads();

        const float* xrow = xs[bt&1] + sidx*16;
        #pragma unroll
        for (int r = 0; r < LB; ++r) {
            u64 p2[4] = {0ull, 0ull, 0ull, 0ull};
            #pragma unroll
            for (int j = 0; j < 4; ++j) {
                int je = (j + swz) & 3;
                ulonglong2 v = *(const ulonglong2*)(xrow + r*CC + je*4);
                #pragma unroll
                for (int g = 0; g < 4; ++g) {
                    ffma2(p2[g], v.x, w2[g][2*je]);
                    ffma2(p2[g], v.y, w2[g][2*je+1]);
                }
            }
            float pv[4];
            #pragma unroll
            for (int g = 0; g < 4; ++g) {
                float lo, hi; unpack2(p2[g], lo, hi);
                float v = lo + hi;
                v += __shfl_xor_sync(0xffffffffu, v, 4);
                v += __shfl_xor_sync(0xffffffffu, v, 8);
                v += __shfl_xor_sync(0xffffffffu, v, 16);
                pv[g] = v;
            }
            if (lane < 4) {
                #pragma unroll
                for (int g = 0; g < 4; ++g)
                    s_red[(r*8 + w)*16 + lane + 4*g] = pv[g];
            }
        }
        __syncthreads();
        if (t < 64) {
            int r = t >> 4, h = t & 15;
            float s = 0.f;
            #pragma unroll
            for (int ww = 0; ww < 8; ++ww) s += s_red[(r*8 + ww)*16 + h];
            g_att[((size_t)b*HH + h)*NN + n_base + bt*LB + r] = s;
        }
        if (bt + 2 < LR/LB) L_ISSUE(bt + 2);
    }
    #undef L_ISSUE
}

// ---------------------------------------------------------------------------
// Kernel 3: softmax over n per (b,h); exp in place + denom.
// ---------------------------------------------------------------------------
__global__ void k_softmax() {
    int bh = blockIdx.x;              // 0..255
    int t  = threadIdx.x;             // 256
    float4* row4 = (float4*)(g_att + (size_t)bh * NN);
    __shared__ float sred[256];

    float m = -1e30f;
    #pragma unroll
    for (int i = t; i < NN/4; i += 256) {
        float4 v = row4[i];
        m = fmaxf(m, fmaxf(fmaxf(v.x, v.y), fmaxf(v.z, v.w)));
    }
    sred[t] = m; __syncthreads();
    for (int s = 128; s > 0; s >>= 1) {
        if (t < s) sred[t] = fmaxf(sred[t], sred[t+s]);
        __syncthreads();
    }
    m = sred[0]; __syncthreads();

    float sum = 0.f;
    #pragma unroll
    for (int i = t; i < NN/4; i += 256) {
        float4 v = row4[i];
        v.x = __expf(v.x - m); v.y = __expf(v.y - m);
        v.z = __expf(v.z - m); v.w = __expf(v.w - m);
        row4[i] = v;
        sum += (v.x + v.y) + (v.z + v.w);
    }
    sred[t] = sum; __syncthreads();
    for (int s = 128; s > 0; s >>= 1) {
        if (t < s) sred[t] += sred[t+s];
        __syncthreads();
    }
    if (t == 0) g_denom[bh] = sred[0];
}

// ---------------------------------------------------------------------------
// Kernel 4 (big pass 2): xa_part[p][b][h][c] = sum_{n in part p} att * x.
// x staged via cp.async; each thread consumes only bytes it staged itself ->
// NO __syncthreads in the mainloop (wait_group suffices). Plain STG.128
// epilogue to private partial tile (no atomics).
// ---------------------------------------------------------------------------
#define XR 128
#define XB 4
__global__ void __launch_bounds__(256, 2) k_xa(const float* __restrict__ x) {
    int part   = blockIdx.x;          // 0..31
    int b      = blockIdx.y;
    int n_base = part * XR;
    int t      = threadIdx.x;

    __shared__ __align__(16) float xs[2][XB*CC];   // 32 KB
    __shared__ __align__(16) float ps[XR*16];      // 8 KB  [n_local][h]

    const float* xb = x + ((size_t)b*NN + n_base)*CC;

    #define X_ISSUE(bt) do {                                              \
        const float* _s = xb + (size_t)(bt)*XB*CC + t*4;                  \
        float* _d = xs[(bt)&1] + t*4;                                     \
        _Pragma("unroll")                                                 \
        for (int _r = 0; _r < XB; ++_r) cp16(_d + _r*CC, _s + _r*CC);     \
        cp_commit();                                                      \
    } while (0)

    X_ISSUE(0);
    X_ISSUE(1);

    // stage probs [XR rows x 16 heads]
    {
        int h = t & 15, rg = t >> 4;   // rg 0..15 -> rows rg*8 .. rg*8+8
        const float* ar = g_att + ((size_t)b*HH + h)*NN + n_base + rg*8;
        #pragma unroll
        for (int i = 0; i < 8; i += 4) {
            float4 a4 = *(const float4*)(ar + i);
            ps[(rg*8 + i + 0)*16 + h] = a4.x;
            ps[(rg*8 + i + 1)*16 + h] = a4.y;
            ps[(rg*8 + i + 2)*16 + h] = a4.z;
            ps[(rg*8 + i + 3)*16 + h] = a4.w;
        }
    }
    __syncthreads();   // ps visible to all; xs handled per-thread by wait_group

    u64 acc[8][4];
    #pragma unroll
    for (int hp = 0; hp < 8; ++hp)
        #pragma unroll
        for (int cj = 0; cj < 4; ++cj) acc[hp][cj] = 0ull;

    for (int bt = 0; bt < XR/XB; ++bt) {
        if (bt + 1 < XR/XB) cp_wait<1>(); else cp_wait<0>();

        #pragma unroll
        for (int r = 0; r < XB; ++r) {
            int nl = bt*XB + r;
            float4 xv = *(const float4*)(xs[bt&1] + r*CC + t*4);

            const ulonglong2* pr = (const ulonglong2*)(ps + nl*16);
            ulonglong2 q0 = pr[0], q1 = pr[1], q2 = pr[2], q3 = pr[3];
            u64 pp[8] = {q0.x, q0.y, q1.x, q1.y, q2.x, q2.y, q3.x, q3.y};

            u64 xx0 = pack2(xv.x, xv.x);
            u64 xx1 = pack2(xv.y, xv.y);
            u64 xx2 = pack2(xv.z, xv.z);
            u64 xx3 = pack2(xv.w, xv.w);

            #pragma unroll
            for (int hp = 0; hp < 8; ++hp) {
                ffma2(acc[hp][0], pp[hp], xx0);
                ffma2(acc[hp][1], pp[hp], xx1);
                ffma2(acc[hp][2], pp[hp], xx2);
                ffma2(acc[hp][3], pp[hp], xx3);
            }
        }
        if (bt + 2 < XR/XB) X_ISSUE(bt + 2);
    }
    #undef X_ISSUE

    // epilogue: plain vector stores to private partial tile
    int c0 = t * 4;
    float* base = g_xap + (((size_t)part*BB + b)*HH)*CC;
    #pragma unroll
    for (int hp = 0; hp < 8; ++hp) {
        float4 vlo, vhi;
        unpack2(acc[hp][0], vlo.x, vhi.x);
        unpack2(acc[hp][1], vlo.y, vhi.y);
        unpack2(acc[hp][2], vlo.z, vhi.z);
        unpack2(acc[hp][3], vlo.w, vhi.w);
        *(float4*)(base + (size_t)(2*hp    )*CC + c0) = vlo;
        *(float4*)(base + (size_t)(2*hp + 1)*CC + c0) = vhi;
    }
}

// ---------------------------------------------------------------------------
// Kernel 4b: fold the 32 partial tiles into g_xa (pure streaming, ~5us).
// ---------------------------------------------------------------------------
__global__ void k_xared() {
    int bh = blockIdx.x;   // 0..255
    int t  = threadIdx.x;  // 256
    int c  = t * 4;
    float4 s = make_float4(0.f, 0.f, 0.f, 0.f);
    #pragma unroll
    for (int p = 0; p < XPARTS; ++p) {
        float4 v = *(const float4*)(g_xap + ((size_t)p*BB*HH + bh)*CC + c);
        s.x += v.x; s.y += v.y; s.z += v.z; s.w += v.w;
    }
    *(float4*)(g_xa + (size_t)bh*CC + c) = s;
}

// ---------------------------------------------------------------------------
// Kernel 5: cls[b,h,d] = (1/denom) * sum_c xa[b,h,c] * Wkv_v[c,h,d]
// Also seeds out with bproj (k_proj atomic-adds on top).
// ---------------------------------------------------------------------------
__global__ void k_cls(const float* __restrict__ Wkv,
                      const float* __restrict__ bproj,
                      float* __restrict__ out) {
    int b = blockIdx.x >> 4, h = blockIdx.x & 15;
    int d = threadIdx.x;   // 64
    __shared__ float xas[CC];
    const float* xa = g_xa + ((size_t)b*HH + h)*CC;
    for (int c = d; c < CC; c += 64) xas[c] = xa[c];
    __syncthreads();

    const float* wv = Wkv + (HH*DD) + h*DD + d;   // v-half column offset 1024
    float acc = 0.f;
    #pragma unroll 8
    for (int c = 0; c < CC; ++c)
        acc += xas[c] * wv[(size_t)c * (2*HH*DD)];

    float inv = 1.0f / g_denom[b*HH + h];
    int col = h*DD + d;
    g_cls[(size_t)b*CC + col] = acc * inv;
    out[(size_t)b*CC + col]   = bproj[col];
}

// ---------------------------------------------------------------------------
// Kernel 6: out[b,j] += sum_i cls[b,i] * Wproj[i,j]
// ---------------------------------------------------------------------------
__global__ void k_proj(const float* __restrict__ Wproj,
                       float* __restrict__ out) {
    int jc = blockIdx.x;   // 0..3
    int ic = blockIdx.y;   // 0..3
    int b  = blockIdx.z;   // 0..15
    int tt = threadIdx.x;  // 256
    int j  = jc*256 + tt;

    __shared__ float cs[256];
    cs[tt] = g_cls[(size_t)b*CC + ic*256 + tt];
    __syncthreads();

    const float* wp = Wproj + (size_t)(ic*256) * CC + j;
    float acc = 0.f;
    #pragma unroll 8
    for (int i = 0; i < 256; ++i)
        acc += cs[i] * wp[(size_t)i * CC];
    atomicAdd(&out[(size_t)b*CC + j], acc);
}

// ---------------------------------------------------------------------------
extern "C" void kernel_launch(void* const* d_in, const int* in_sizes, int n_in,
                              void* d_out, int out_size) {
    const float* x     = (const float*)d_in[0];
    const float* Wq    = (const float*)d_in[1];
    const float* Wkv   = (const float*)d_in[2];
    const float* Wproj = (const float*)d_in[3];
    const float* bproj = (const float*)d_in[4];
    float* out = (float*)d_out;

    k_watt   <<<BB*HH, 256>>>(x, Wq, Wkv);
    k_logits <<<dim3(NN/LR, BB), 256>>>(x);
    k_softmax<<<BB*HH, 256>>>();
    k_xa     <<<dim3(NN/XR, BB), 256>>>(x);
    k_xared  <<<BB*HH, 256>>>();
    k_cls    <<<BB*HH, 64>>>(Wkv, bproj, out);
    k_proj   <<<dim3(4, 4, BB), 256>>>(Wproj, out);
}